// round 14
// baseline (speedup 1.0000x reference)
#include <cuda_runtime.h>
#include <cstdint>
#include <cstddef>

// Problem constants
static const int B  = 512;
static const int S  = 100;
static const int H  = 256;

#define TINYF 1.17549435e-38f

// ---------------- scratch (device globals; no allocations allowed) ----------------
__device__ float d_enc [512 * 100 * 256];              // [b][s][h]
__device__ float d_refg[512 * 100 * 256];              // [b][s][h]
__device__ float d_refp[512 * 100 * 256];              // [b][s][h]
__device__ float d_h[512 * 256];                       // encoder final h
__device__ float d_c[512 * 256];                       // encoder final c
__device__ float d_gum[100 * 512 * 100];               // gumbel noise per (t,b,s)
__device__ float d_Menc[2 * 1024];                     // emb @ enc_Wih^T   (rank-2 factor)
__device__ float d_Mdec[2 * 1024];                     // emb @ dec_Wih^T
__device__ float d_xstart[1024];                       // start @ dec_Wih^T

// ---------------- helpers ----------------
__device__ __forceinline__ float sigf(float x) { return 1.0f / (1.0f + expf(-x)); }
__device__ __forceinline__ float neg_inf() { return __int_as_float((int)0xff800000); }

// Threefry-2x32, 20 rounds (matches JAX threefry2x32_p)
__device__ __forceinline__ void threefry2x32(uint32_t k0, uint32_t k1,
                                             uint32_t x0, uint32_t x1,
                                             uint32_t* o0, uint32_t* o1)
{
    uint32_t ks2 = k0 ^ k1 ^ 0x1BD11BDAu;
#define TFR(r) { x0 += x1; x1 = (x1 << (r)) | (x1 >> (32 - (r))); x1 ^= x0; }
    x0 += k0;  x1 += k1;
    TFR(13) TFR(15) TFR(26) TFR(6)
    x0 += k1;  x1 += ks2 + 1u;
    TFR(17) TFR(29) TFR(16) TFR(24)
    x0 += ks2; x1 += k0 + 2u;
    TFR(13) TFR(15) TFR(26) TFR(6)
    x0 += k0;  x1 += k1 + 3u;
    TFR(17) TFR(29) TFR(16) TFR(24)
    x0 += k1;  x1 += ks2 + 4u;
    TFR(13) TFR(15) TFR(26) TFR(6)
    x0 += ks2; x1 += k0 + 5u;
#undef TFR
    *o0 = x0; *o1 = x1;
}

// ---------------- gumbel noise ----------------
__global__ void gumbelk()
{
    int i = blockIdx.x * blockDim.x + threadIdx.x;
    if (i >= S * B * S) return;
    int step   = i / (B * S);
    uint32_t n = (uint32_t)(i - step * (B * S));
    uint32_t k0, k1;
    threefry2x32(0u, 1u, 0u, (uint32_t)step, &k0, &k1);
    uint32_t a, bb;
    threefry2x32(k0, k1, 0u, n, &a, &bb);
    uint32_t bits = a ^ bb;
    float f = __uint_as_float((bits >> 9) | 0x3f800000u) - 1.0f;
    float u = fmaxf(TINYF, f + TINYF);
    d_gum[i] = -logf(-logf(u));
}

// ---------------- tiny precompute: rank-2 factors + start projection ----------------
__global__ void precompk(const float* __restrict__ emb,
                         const float* __restrict__ enc_Wih,
                         const float* __restrict__ dec_Wih,
                         const float* __restrict__ start)
{
    int j = blockIdx.x * blockDim.x + threadIdx.x;
    if (j >= 1024) return;
    float m0 = 0.f, m1 = 0.f, n0 = 0.f, n1 = 0.f, xs = 0.f;
    for (int e = 0; e < 256; e++) {
        float we = enc_Wih[(size_t)j * 256 + e];
        float wd = dec_Wih[(size_t)j * 256 + e];
        m0 = fmaf(emb[e],       we, m0);
        m1 = fmaf(emb[256 + e], we, m1);
        n0 = fmaf(emb[e],       wd, n0);
        n1 = fmaf(emb[256 + e], wd, n1);
        xs = fmaf(start[e],     wd, xs);
    }
    d_Menc[j] = m0; d_Menc[1024 + j] = m1;
    d_Mdec[j] = n0; d_Mdec[1024 + j] = n1;
    d_xstart[j] = xs;
}

// ================= persistent encoder + fused ref projections =====================
// 256 blocks x 256 threads, 2 batch rows/block, 2 blocks/SM.
// Thread hh owns: 4 gate columns (hh+256g) + cell + ref projections, rows 0..1.
__global__ void __launch_bounds__(256, 2)
encoderk(const float* __restrict__ inputs,
         const float* __restrict__ Whh,
         const float* __restrict__ bih, const float* __restrict__ bhh,
         const float* __restrict__ gWr, const float* __restrict__ gbr,
         const float* __restrict__ pWr, const float* __restrict__ pbr)
{
    const int hh = threadIdx.x;
    const int b0 = blockIdx.x * 2;

    __shared__ __align__(16) float hs[2][256];

    float creg[2] = {0.f, 0.f};
    float me0[4], me1[4], bi1[4], bi2[4];
#pragma unroll
    for (int g = 0; g < 4; g++) {
        int j = hh + 256 * g;
        me0[g] = d_Menc[j]; me1[g] = d_Menc[1024 + j];
        bi1[g] = bih[j];    bi2[g] = bhh[j];
    }
    const float gbr_t = gbr[hh];
    const float pbr_t = pbr[hh];

    hs[0][hh] = 0.0f;
    hs[1][hh] = 0.0f;
    __syncthreads();

    for (int s = 0; s < S; s++) {
        // ---- gates: thread hh computes cols hh+256g for rows 0..1 (full K) ----
        float acc[4][2];
#pragma unroll
        for (int g = 0; g < 4; g++) { acc[g][0] = 0.f; acc[g][1] = 0.f; }
#pragma unroll 2
        for (int kg = 0; kg < 64; kg++) {
            int k = kg * 4;
            float4 x0 = *(const float4*)&hs[0][k];
            float4 x1 = *(const float4*)&hs[1][k];
#pragma unroll
            for (int g = 0; g < 4; g++) {
                float4 w = *(const float4*)&Whh[(size_t)(hh + 256 * g) * 256 + k];
                acc[g][0] = fmaf(w.x, x0.x, acc[g][0]); acc[g][0] = fmaf(w.y, x0.y, acc[g][0]);
                acc[g][0] = fmaf(w.z, x0.z, acc[g][0]); acc[g][0] = fmaf(w.w, x0.w, acc[g][0]);
                acc[g][1] = fmaf(w.x, x1.x, acc[g][1]); acc[g][1] = fmaf(w.y, x1.y, acc[g][1]);
                acc[g][1] = fmaf(w.z, x1.z, acc[g][1]); acc[g][1] = fmaf(w.w, x1.w, acc[g][1]);
            }
        }
        __syncthreads();                 // done reading hs (s-1)
        // ---- cell inline (gates never touch SMEM) ----
#pragma unroll
        for (int r = 0; r < 2; r++) {
            int b = b0 + r;
            float i0 = inputs[((size_t)b * 2 + 0) * S + s];
            float i1 = inputs[((size_t)b * 2 + 1) * S + s];
            float pre[4];
#pragma unroll
            for (int g = 0; g < 4; g++) {
                float xv = fmaf(i1, me1[g], i0 * me0[g]);
                pre[g] = acc[g][r] + ((xv + bi1[g]) + bi2[g]);   // R10 encoder order
            }
            float ig = sigf(pre[0]);
            float fg = sigf(pre[1]);
            float gg = tanhf(pre[2]);
            float og = sigf(pre[3]);
            float c  = fg * creg[r] + ig * gg;
            creg[r]  = c;
            float h  = og * tanhf(c);
            hs[r][hh] = h;
            d_enc[((size_t)b * S + s) * H + hh] = h;
        }
        __syncthreads();                 // hs (s) visible

        // ---- fused ref projections of h_s (full K, no reduction) ----
        {
            float rg[2] = {0.f, 0.f}, rp[2] = {0.f, 0.f};
            const float* wg = gWr + (size_t)hh * 256;
            const float* wp = pWr + (size_t)hh * 256;
#pragma unroll 2
            for (int kg = 0; kg < 64; kg++) {
                int k = kg * 4;
                float4 ag = *(const float4*)(wg + k);
                float4 ap = *(const float4*)(wp + k);
                float4 h0 = *(const float4*)&hs[0][k];
                float4 h1 = *(const float4*)&hs[1][k];
                rg[0] = fmaf(ag.x, h0.x, rg[0]); rg[0] = fmaf(ag.y, h0.y, rg[0]);
                rg[0] = fmaf(ag.z, h0.z, rg[0]); rg[0] = fmaf(ag.w, h0.w, rg[0]);
                rg[1] = fmaf(ag.x, h1.x, rg[1]); rg[1] = fmaf(ag.y, h1.y, rg[1]);
                rg[1] = fmaf(ag.z, h1.z, rg[1]); rg[1] = fmaf(ag.w, h1.w, rg[1]);
                rp[0] = fmaf(ap.x, h0.x, rp[0]); rp[0] = fmaf(ap.y, h0.y, rp[0]);
                rp[0] = fmaf(ap.z, h0.z, rp[0]); rp[0] = fmaf(ap.w, h0.w, rp[0]);
                rp[1] = fmaf(ap.x, h1.x, rp[1]); rp[1] = fmaf(ap.y, h1.y, rp[1]);
                rp[1] = fmaf(ap.z, h1.z, rp[1]); rp[1] = fmaf(ap.w, h1.w, rp[1]);
            }
#pragma unroll
            for (int r = 0; r < 2; r++) {
                size_t o = ((size_t)(b0 + r) * S + s) * H + hh;
                d_refg[o] = rg[r] + gbr_t;
                d_refp[o] = rp[r] + pbr_t;
            }
        }
        // no sync: next gates phase only reads hs; next hs write is after its sync
    }
#pragma unroll
    for (int r = 0; r < 2; r++) {
        d_h[(size_t)(b0 + r) * H + hh] = hs[r][hh];
        d_c[(size_t)(b0 + r) * H + hh] = creg[r];
    }
}

// ================= persistent decoder: 2 rows/block, 256 threads, 2 blocks/SM =====
__global__ void __launch_bounds__(256, 2)
decoderk(const float* __restrict__ inputs,
         const float* __restrict__ Whh,
         const float* __restrict__ bih, const float* __restrict__ bhh,
         const float* __restrict__ gWq, const float* __restrict__ gbq,
         const float* __restrict__ gV,
         const float* __restrict__ pWq, const float* __restrict__ pbq,
         const float* __restrict__ pV,
         float* __restrict__ out_probs, float* __restrict__ out_idx)
{
    const int hh   = threadIdx.x;
    const int lane = hh & 31;
    const int w    = hh >> 5;            // 0..7
    const int b0   = blockIdx.x * 2;

    __shared__ __align__(16) float hs [2][256];
    __shared__ __align__(16) float qs [2][256];     // qq, then readout q
    __shared__ __align__(16) float qps[2][256];
    __shared__ float lgm[2][100];
    __shared__ float pr [2][100];
    __shared__ float sa0[2], sa1[2];
    __shared__ unsigned char msk[2][104];

    float creg[2];

    // hoisted constants
    float md0[4], md1[4], bi1[4], bi2[4], xst[4];
#pragma unroll
    for (int g = 0; g < 4; g++) {
        int j = hh + 256 * g;
        md0[g] = d_Mdec[j]; md1[g] = d_Mdec[1024 + j];
        bi1[g] = bih[j];    bi2[g] = bhh[j];
        xst[g] = d_xstart[j];
    }
    const float gbq_t = gbq[hh];
    const float pbq_t = pbq[hh];
    float gvv[8], pvv[8];
#pragma unroll
    for (int k = 0; k < 8; k++) { gvv[k] = gV[k * 32 + lane]; pvv[k] = pV[k * 32 + lane]; }

#pragma unroll
    for (int r = 0; r < 2; r++) {
        hs[r][hh] = d_h[(size_t)(b0 + r) * H + hh];
        creg[r]   = d_c[(size_t)(b0 + r) * H + hh];
        msk[r][hh & 127] = 0;            // covers 0..103 (some redundant writes ok)
    }
    __syncthreads();

    for (int t = 0; t < S; t++) {
        // ======== LSTM gates: thread hh, cols hh+256g, rows 0..1, full K ========
        float acc[4][2];
#pragma unroll
        for (int g = 0; g < 4; g++) { acc[g][0] = 0.f; acc[g][1] = 0.f; }
#pragma unroll 2
        for (int kg = 0; kg < 64; kg++) {
            int k = kg * 4;
            float4 x0 = *(const float4*)&hs[0][k];
            float4 x1 = *(const float4*)&hs[1][k];
#pragma unroll
            for (int g = 0; g < 4; g++) {
                float4 wv = *(const float4*)&Whh[(size_t)(hh + 256 * g) * 256 + k];
                acc[g][0] = fmaf(wv.x, x0.x, acc[g][0]); acc[g][0] = fmaf(wv.y, x0.y, acc[g][0]);
                acc[g][0] = fmaf(wv.z, x0.z, acc[g][0]); acc[g][0] = fmaf(wv.w, x0.w, acc[g][0]);
                acc[g][1] = fmaf(wv.x, x1.x, acc[g][1]); acc[g][1] = fmaf(wv.y, x1.y, acc[g][1]);
                acc[g][1] = fmaf(wv.z, x1.z, acc[g][1]); acc[g][1] = fmaf(wv.w, x1.w, acc[g][1]);
            }
        }
        __syncthreads();                 // done reading hs (t-1)
        // ======== cell inline ========
#pragma unroll
        for (int r = 0; r < 2; r++) {
            float pre[4];
#pragma unroll
            for (int g = 0; g < 4; g++) {
                float xv = (t == 0) ? xst[g] : fmaf(sa1[r], md1[g], sa0[r] * md0[g]);
                pre[g] = ((acc[g][r] + xv) + bi1[g]) + bi2[g];   // R10 decoder order
            }
            float ig = sigf(pre[0]);
            float fg = sigf(pre[1]);
            float gg = tanhf(pre[2]);
            float og = sigf(pre[3]);
            float c  = fg * creg[r] + ig * gg;
            creg[r]  = c;
            hs[r][hh] = og * tanhf(c);
        }
        __syncthreads();                 // hs (t) visible

        // ======== qq = h @ gWq^T + gbq (thread hh, rows 0..1, full K) ========
        {
            float a0 = 0.f, a1 = 0.f;
            const float* wrow = gWq + (size_t)hh * 256;
#pragma unroll 2
            for (int kg = 0; kg < 64; kg++) {
                int k = kg * 4;
                float4 wv = *(const float4*)(wrow + k);
                float4 h0 = *(const float4*)&hs[0][k];
                float4 h1 = *(const float4*)&hs[1][k];
                a0 = fmaf(wv.x, h0.x, a0); a0 = fmaf(wv.y, h0.y, a0);
                a0 = fmaf(wv.z, h0.z, a0); a0 = fmaf(wv.w, h0.w, a0);
                a1 = fmaf(wv.x, h1.x, a1); a1 = fmaf(wv.y, h1.y, a1);
                a1 = fmaf(wv.z, h1.z, a1); a1 = fmaf(wv.w, h1.w, a1);
            }
            qs[0][hh] = a0 + gbq_t;
            qs[1][hh] = a1 + gbq_t;
        }
        __syncthreads();

        // ======== glimpse logits: 8 warps, r = w>>2, quarter = w&3, 25 s each ====
        {
            int r  = w >> 2;
            int s0 = (w & 3) * 25;
            float qv[8];
#pragma unroll
            for (int k = 0; k < 8; k++) qv[k] = qs[r][k * 32 + lane];
#pragma unroll 2
            for (int si = 0; si < 25; si++) {
                int s = s0 + si;
                const float* rp = &d_refg[(((size_t)(b0 + r)) * S + s) * H];
                float sum = 0.0f;
#pragma unroll
                for (int k = 0; k < 8; k++)
                    sum = fmaf(gvv[k], tanhf(qv[k] + __ldg(&rp[k * 32 + lane])), sum);
#pragma unroll
                for (int o = 16; o > 0; o >>= 1) sum += __shfl_xor_sync(0xffffffffu, sum, o);
                if (lane == 0) lgm[r][s] = msk[r][s] ? neg_inf() : sum;
            }
        }
        __syncthreads();

        // ======== glimpse softmax -> pr (bit-identical per-row) ========
        if (w < 2) {
            int r = w;
            float v[4];
#pragma unroll
            for (int j = 0; j < 4; j++) {
                int s = lane + 32 * j;
                v[j] = (s < 100) ? lgm[r][s] : neg_inf();
            }
            float m = fmaxf(fmaxf(v[0], v[1]), fmaxf(v[2], v[3]));
#pragma unroll
            for (int o = 16; o > 0; o >>= 1) m = fmaxf(m, __shfl_xor_sync(0xffffffffu, m, o));
            float e[4];
#pragma unroll
            for (int j = 0; j < 4; j++) {
                int s = lane + 32 * j;
                e[j] = (s < 100) ? expf(v[j] - m) : 0.0f;
            }
            float sum = (e[0] + e[2]) + (e[1] + e[3]);
#pragma unroll
            for (int o = 16; o > 0; o >>= 1) sum += __shfl_xor_sync(0xffffffffu, sum, o);
#pragma unroll
            for (int j = 0; j < 4; j++) {
                int s = lane + 32 * j;
                if (s < 100) pr[r][s] = e[j] / sum;
            }
        }
        __syncthreads();

        // ======== readout: q[r][hh] = sum_s pr[r][s]*enc[b][s][hh] (ascending s) ==
        {
            float a0 = 0.f, a1 = 0.f;
            const float* e0 = &d_enc[(size_t)(b0 + 0) * S * H + hh];
            const float* e1 = &d_enc[(size_t)(b0 + 1) * S * H + hh];
            for (int s = 0; s < S; s++) {
                a0 = fmaf(pr[0][s], __ldg(e0 + (size_t)s * H), a0);
                a1 = fmaf(pr[1][s], __ldg(e1 + (size_t)s * H), a1);
            }
            qs[0][hh] = a0;
            qs[1][hh] = a1;
        }
        __syncthreads();

        // ======== qp = q @ pWq^T + pbq ========
        {
            float a0 = 0.f, a1 = 0.f;
            const float* wrow = pWq + (size_t)hh * 256;
#pragma unroll 2
            for (int kg = 0; kg < 64; kg++) {
                int k = kg * 4;
                float4 wv = *(const float4*)(wrow + k);
                float4 h0 = *(const float4*)&qs[0][k];
                float4 h1 = *(const float4*)&qs[1][k];
                a0 = fmaf(wv.x, h0.x, a0); a0 = fmaf(wv.y, h0.y, a0);
                a0 = fmaf(wv.z, h0.z, a0); a0 = fmaf(wv.w, h0.w, a0);
                a1 = fmaf(wv.x, h1.x, a1); a1 = fmaf(wv.y, h1.y, a1);
                a1 = fmaf(wv.z, h1.z, a1); a1 = fmaf(wv.w, h1.w, a1);
            }
            qps[0][hh] = a0 + pbq_t;
            qps[1][hh] = a1 + pbq_t;
        }
        __syncthreads();

        // ======== pointer logits ========
        {
            int r  = w >> 2;
            int s0 = (w & 3) * 25;
            float qv[8];
#pragma unroll
            for (int k = 0; k < 8; k++) qv[k] = qps[r][k * 32 + lane];
#pragma unroll 2
            for (int si = 0; si < 25; si++) {
                int s = s0 + si;
                const float* rp = &d_refp[(((size_t)(b0 + r)) * S + s) * H];
                float sum = 0.0f;
#pragma unroll
                for (int k = 0; k < 8; k++)
                    sum = fmaf(pvv[k], tanhf(qv[k] + __ldg(&rp[k * 32 + lane])), sum);
#pragma unroll
                for (int o = 16; o > 0; o >>= 1) sum += __shfl_xor_sync(0xffffffffu, sum, o);
                if (lane == 0) lgm[r][s] = msk[r][s] ? neg_inf() : (10.0f * tanhf(sum));
            }
        }
        __syncthreads();

        // ======== sample (bit-identical per-row) ========
        if (w < 2) {
            int r = w;
            int b = b0 + r;
            float v[4];
#pragma unroll
            for (int j = 0; j < 4; j++) {
                int s = lane + 32 * j;
                v[j] = (s < 100) ? lgm[r][s] : neg_inf();
            }
            float bv = neg_inf(); int bi = 0;
#pragma unroll
            for (int j = 0; j < 4; j++) {
                int s = lane + 32 * j;
                if (s < 100) {
                    float y = v[j] + d_gum[((size_t)t * B + b) * S + s];
                    if (y > bv) { bv = y; bi = s; }
                }
            }
#pragma unroll
            for (int o = 16; o > 0; o >>= 1) {
                float vo = __shfl_xor_sync(0xffffffffu, bv, o);
                int   io = __shfl_xor_sync(0xffffffffu, bi, o);
                if (vo > bv || (vo == bv && io < bi)) { bv = vo; bi = io; }
            }
            float m = fmaxf(fmaxf(v[0], v[1]), fmaxf(v[2], v[3]));
#pragma unroll
            for (int o = 16; o > 0; o >>= 1) m = fmaxf(m, __shfl_xor_sync(0xffffffffu, m, o));
            float e[4];
#pragma unroll
            for (int j = 0; j < 4; j++) {
                int s = lane + 32 * j;
                e[j] = (s < 100) ? expf(v[j] - m) : 0.0f;
            }
            float sum = (e[0] + e[2]) + (e[1] + e[3]);
#pragma unroll
            for (int o = 16; o > 0; o >>= 1) sum += __shfl_xor_sync(0xffffffffu, sum, o);
#pragma unroll
            for (int j = 0; j < 4; j++) {
                int s = lane + 32 * j;
                if (s < 100) out_probs[((size_t)t * B + b) * S + s] = e[j] / sum;
            }
            if (lane == 0) {
                msk[r][bi] = 1;
                out_idx[(size_t)t * B + b] = (float)bi;
                sa0[r] = inputs[((size_t)b * 2 + 0) * S + bi];
                sa1[r] = inputs[((size_t)b * 2 + 1) * S + bi];
            }
        }
        __syncthreads();
    }
}

// ---------------- host ----------------
extern "C" void kernel_launch(void* const* d_in, const int* in_sizes, int n_in,
                              void* d_out, int out_size)
{
    (void)in_sizes; (void)n_in; (void)out_size;
    const float* inputs  = (const float*)d_in[0];
    const float* emb     = (const float*)d_in[1];
    const float* enc_Wih = (const float*)d_in[2];
    const float* enc_Whh = (const float*)d_in[3];
    const float* enc_bih = (const float*)d_in[4];
    const float* enc_bhh = (const float*)d_in[5];
    const float* dec_Wih = (const float*)d_in[6];
    const float* dec_Whh = (const float*)d_in[7];
    const float* dec_bih = (const float*)d_in[8];
    const float* dec_bhh = (const float*)d_in[9];
    const float* g_Wq    = (const float*)d_in[10];
    const float* g_bq    = (const float*)d_in[11];
    const float* g_Wr    = (const float*)d_in[12];
    const float* g_br    = (const float*)d_in[13];
    const float* g_V     = (const float*)d_in[14];
    const float* p_Wq    = (const float*)d_in[15];
    const float* p_bq    = (const float*)d_in[16];
    const float* p_Wr    = (const float*)d_in[17];
    const float* p_br    = (const float*)d_in[18];
    const float* p_V     = (const float*)d_in[19];
    const float* start   = (const float*)d_in[20];

    float* out       = (float*)d_out;
    float* out_probs = out;                              // [S,B,S]
    float* out_idx   = out + (size_t)S * B * S;          // [S,B] (as float)

    gumbelk <<<(S * B * S + 255) / 256, 256>>>();
    precompk<<<4, 256>>>(emb, enc_Wih, dec_Wih, start);

    encoderk<<<B / 2, 256>>>(inputs, enc_Whh, enc_bih, enc_bhh,
                             g_Wr, g_br, p_Wr, p_br);

    decoderk<<<B / 2, 256>>>(inputs, dec_Whh, dec_bih, dec_bhh,
                             g_Wq, g_bq, g_V, p_Wq, p_bq, p_V,
                             out_probs, out_idx);
}

// round 17
// speedup vs baseline: 1.6577x; 1.6577x over previous
#include <cuda_runtime.h>
#include <cstdint>
#include <cstddef>

// Problem constants
static const int B  = 512;
static const int S  = 100;
static const int H  = 256;

#define TINYF 1.17549435e-38f

// ---------------- scratch (device globals; no allocations allowed) ----------------
__device__ float d_enc [512 * 100 * 256];              // [b][s][h]
__device__ float d_refg[512 * 100 * 256];              // [b][s][h]
__device__ float d_refp[512 * 100 * 256];              // [b][s][h]
__device__ float d_h[512 * 256];                       // encoder final h
__device__ float d_c[512 * 256];                       // encoder final c
__device__ float d_gum[100 * 512 * 100];               // gumbel noise per (t,b,s)
__device__ float d_Menc[2 * 1024];                     // emb @ enc_Wih^T   (rank-2 factor)
__device__ float d_Mdec[2 * 1024];                     // emb @ dec_Wih^T
__device__ float d_xstart[1024];                       // start @ dec_Wih^T

// ---------------- helpers ----------------
__device__ __forceinline__ float sigf(float x) { return 1.0f / (1.0f + expf(-x)); }
__device__ __forceinline__ float neg_inf() { return __int_as_float((int)0xff800000); }

// Threefry-2x32, 20 rounds (matches JAX threefry2x32_p)
__device__ __forceinline__ void threefry2x32(uint32_t k0, uint32_t k1,
                                             uint32_t x0, uint32_t x1,
                                             uint32_t* o0, uint32_t* o1)
{
    uint32_t ks2 = k0 ^ k1 ^ 0x1BD11BDAu;
#define TFR(r) { x0 += x1; x1 = (x1 << (r)) | (x1 >> (32 - (r))); x1 ^= x0; }
    x0 += k0;  x1 += k1;
    TFR(13) TFR(15) TFR(26) TFR(6)
    x0 += k1;  x1 += ks2 + 1u;
    TFR(17) TFR(29) TFR(16) TFR(24)
    x0 += ks2; x1 += k0 + 2u;
    TFR(13) TFR(15) TFR(26) TFR(6)
    x0 += k0;  x1 += k1 + 3u;
    TFR(17) TFR(29) TFR(16) TFR(24)
    x0 += k1;  x1 += ks2 + 4u;
    TFR(13) TFR(15) TFR(26) TFR(6)
    x0 += ks2; x1 += k0 + 5u;
#undef TFR
    *o0 = x0; *o1 = x1;
}

// ---------------- gumbel noise ----------------
__global__ void gumbelk()
{
    int i = blockIdx.x * blockDim.x + threadIdx.x;
    if (i >= S * B * S) return;
    int step   = i / (B * S);
    uint32_t n = (uint32_t)(i - step * (B * S));
    uint32_t k0, k1;
    threefry2x32(0u, 1u, 0u, (uint32_t)step, &k0, &k1);
    uint32_t a, bb;
    threefry2x32(k0, k1, 0u, n, &a, &bb);
    uint32_t bits = a ^ bb;
    float f = __uint_as_float((bits >> 9) | 0x3f800000u) - 1.0f;
    float u = fmaxf(TINYF, f + TINYF);
    d_gum[i] = -logf(-logf(u));
}

// ---------------- tiny precompute: rank-2 factors + start projection ----------------
__global__ void precompk(const float* __restrict__ emb,
                         const float* __restrict__ enc_Wih,
                         const float* __restrict__ dec_Wih,
                         const float* __restrict__ start)
{
    int j = blockIdx.x * blockDim.x + threadIdx.x;
    if (j >= 1024) return;
    float m0 = 0.f, m1 = 0.f, n0 = 0.f, n1 = 0.f, xs = 0.f;
    for (int e = 0; e < 256; e++) {
        float we = enc_Wih[(size_t)j * 256 + e];
        float wd = dec_Wih[(size_t)j * 256 + e];
        m0 = fmaf(emb[e],       we, m0);
        m1 = fmaf(emb[256 + e], we, m1);
        n0 = fmaf(emb[e],       wd, n0);
        n1 = fmaf(emb[256 + e], wd, n1);
        xs = fmaf(start[e],     wd, xs);
    }
    d_Menc[j] = m0; d_Menc[1024 + j] = m1;
    d_Mdec[j] = n0; d_Mdec[1024 + j] = n1;
    d_xstart[j] = xs;
}

// ---------------- persistent encoder + fused ref projections --------------------
// 128 blocks x 512 threads. 4 batch rows/block. thread = (hh = tid&255, half = tid>>8).
// (bit-identical to the 16.0ms round-10 kernel)
__global__ void __launch_bounds__(512)
encoderk(const float* __restrict__ inputs,
         const float* __restrict__ Whh,
         const float* __restrict__ bih, const float* __restrict__ bhh,
         const float* __restrict__ gWr, const float* __restrict__ gbr,
         const float* __restrict__ pWr, const float* __restrict__ pbr)
{
    const int tid  = threadIdx.x;
    const int hh   = tid & 255;
    const int half = tid >> 8;
    const int k0   = half * 128;
    const int b0   = blockIdx.x * 4;

    __shared__ __align__(16) float hs[4][256];
    __shared__ __align__(16) float red[16][256];

    float creg[4] = {0.f, 0.f, 0.f, 0.f};
    for (int i = tid; i < 1024; i += 512) ((float*)hs)[i] = 0.0f;

    float me0[4], me1[4], bi1[4], bi2[4];
#pragma unroll
    for (int g = 0; g < 4; g++) {
        int j = hh + 256 * g;
        me0[g] = d_Menc[j]; me1[g] = d_Menc[1024 + j];
        bi1[g] = bih[j];    bi2[g] = bhh[j];
    }
    const float gbr_t = gbr[hh];
    const float pbr_t = pbr[hh];
    __syncthreads();

    for (int s = 0; s < S; s++) {
        float acc[4][4];
#pragma unroll
        for (int g = 0; g < 4; g++)
#pragma unroll
            for (int r = 0; r < 4; r++) acc[g][r] = 0.0f;
#pragma unroll 2
        for (int kg = 0; kg < 32; kg++) {
            int k = k0 + kg * 4;
            float4 xv[4];
#pragma unroll
            for (int r = 0; r < 4; r++) xv[r] = *(const float4*)&hs[r][k];
#pragma unroll
            for (int g = 0; g < 4; g++) {
                float4 w = *(const float4*)&Whh[(size_t)(hh + 256 * g) * 256 + k];
#pragma unroll
                for (int r = 0; r < 4; r++) {
                    acc[g][r] = fmaf(w.x, xv[r].x, acc[g][r]);
                    acc[g][r] = fmaf(w.y, xv[r].y, acc[g][r]);
                    acc[g][r] = fmaf(w.z, xv[r].z, acc[g][r]);
                    acc[g][r] = fmaf(w.w, xv[r].w, acc[g][r]);
                }
            }
        }
        if (half == 1) {
#pragma unroll
            for (int g = 0; g < 4; g++)
#pragma unroll
                for (int r = 0; r < 4; r++) red[g * 4 + r][hh] = acc[g][r];
        }
        __syncthreads();

        if (half == 0) {
#pragma unroll
            for (int r = 0; r < 4; r++) {
                int b = b0 + r;
                float a0 = inputs[((size_t)b * 2 + 0) * S + s];
                float a1 = inputs[((size_t)b * 2 + 1) * S + s];
                float pre[4];
#pragma unroll
                for (int g = 0; g < 4; g++) {
                    float hsum = acc[g][r] + red[g * 4 + r][hh];
                    float xv   = fmaf(a1, me1[g], a0 * me0[g]);
                    pre[g] = hsum + ((xv + bi1[g]) + bi2[g]);
                }
                float ig = sigf(pre[0]);
                float fg = sigf(pre[1]);
                float gg = tanhf(pre[2]);
                float og = sigf(pre[3]);
                float c  = fg * creg[r] + ig * gg;
                creg[r]  = c;
                float h  = og * tanhf(c);
                hs[r][hh] = h;
                d_enc[((size_t)b * S + s) * H + hh] = h;
            }
        }
        __syncthreads();

        float rg[4] = {0.f, 0.f, 0.f, 0.f};
        float rp[4] = {0.f, 0.f, 0.f, 0.f};
#pragma unroll 2
        for (int kg = 0; kg < 32; kg++) {
            int k = k0 + kg * 4;
            float4 wg = *(const float4*)&gWr[(size_t)hh * 256 + k];
            float4 wp = *(const float4*)&pWr[(size_t)hh * 256 + k];
#pragma unroll
            for (int r = 0; r < 4; r++) {
                float4 hv = *(const float4*)&hs[r][k];
                rg[r] = fmaf(wg.x, hv.x, rg[r]); rg[r] = fmaf(wg.y, hv.y, rg[r]);
                rg[r] = fmaf(wg.z, hv.z, rg[r]); rg[r] = fmaf(wg.w, hv.w, rg[r]);
                rp[r] = fmaf(wp.x, hv.x, rp[r]); rp[r] = fmaf(wp.y, hv.y, rp[r]);
                rp[r] = fmaf(wp.z, hv.z, rp[r]); rp[r] = fmaf(wp.w, hv.w, rp[r]);
            }
        }
        if (half == 1) {
#pragma unroll
            for (int r = 0; r < 4; r++) { red[r][hh] = rg[r]; red[4 + r][hh] = rp[r]; }
        }
        __syncthreads();
        if (half == 0) {
#pragma unroll
            for (int r = 0; r < 4; r++) {
                size_t o = ((size_t)(b0 + r) * S + s) * H + hh;
                d_refg[o] = (rg[r] + red[r][hh])     + gbr_t;
                d_refp[o] = (rp[r] + red[4 + r][hh]) + pbr_t;
            }
        }
        __syncthreads();
    }
    if (half == 0) {
#pragma unroll
        for (int r = 0; r < 4; r++) {
            d_h[(size_t)(b0 + r) * H + hh] = hs[r][hh];
            d_c[(size_t)(b0 + r) * H + hh] = creg[r];
        }
    }
}

// ---------------- persistent decoder: 4 rows/block, 512 threads -------------------
// R10 structure; attention loops software-unrolled x2 with prefetch (per-s math
// bit-identical). V vectors re-read via __ldg (L1) to keep regs under the cap.
__global__ void __launch_bounds__(512)
decoderk(const float* __restrict__ inputs,
         const float* __restrict__ Whh,
         const float* __restrict__ bih, const float* __restrict__ bhh,
         const float* __restrict__ gWq, const float* __restrict__ gbq,
         const float* __restrict__ gV,
         const float* __restrict__ pWq, const float* __restrict__ pbq,
         const float* __restrict__ pV,
         float* __restrict__ out_probs, float* __restrict__ out_idx)
{
    const int tid  = threadIdx.x;
    const int hh   = tid & 255;
    const int half = tid >> 8;
    const int k0   = half * 128;
    const int lane = tid & 31;
    const int w    = tid >> 5;            // 0..15
    const int b0   = blockIdx.x * 4;

    __shared__ __align__(16) float hs[4][256];
    __shared__ __align__(16) float qs[4][256];     // qq, then readout q
    __shared__ __align__(16) float qps[4][256];
    __shared__ __align__(16) float red[16][256];
    __shared__ float lgm[4][100];
    __shared__ float pr [4][100];
    __shared__ float sa0[4], sa1[4];
    __shared__ unsigned char msk[4][104];

    float creg[4];

    float md0[4], md1[4], bi1[4], bi2[4];
#pragma unroll
    for (int g = 0; g < 4; g++) {
        int j = hh + 256 * g;
        md0[g] = d_Mdec[j]; md1[g] = d_Mdec[1024 + j];
        bi1[g] = bih[j];    bi2[g] = bhh[j];
    }
    float xst[4];
#pragma unroll
    for (int g = 0; g < 4; g++) xst[g] = d_xstart[hh + 256 * g];
    const float gbq_t = gbq[hh];
    const float pbq_t = pbq[hh];

    if (half == 0) {
#pragma unroll
        for (int r = 0; r < 4; r++) {
            hs[r][hh] = d_h[(size_t)(b0 + r) * H + hh];
            creg[r]   = d_c[(size_t)(b0 + r) * H + hh];
        }
    }
    for (int i = tid; i < 4 * 100; i += 512) msk[i / 100][i % 100] = 0;
    __syncthreads();

    for (int t = 0; t < S; t++) {
        // ================= LSTM gates: h @ Whh^T (K-split) + rank-2 input ========
        float acc[4][4];
#pragma unroll
        for (int g = 0; g < 4; g++)
#pragma unroll
            for (int r = 0; r < 4; r++) acc[g][r] = 0.0f;
#pragma unroll 2
        for (int kg = 0; kg < 32; kg++) {
            int k = k0 + kg * 4;
            float4 xv[4];
#pragma unroll
            for (int r = 0; r < 4; r++) xv[r] = *(const float4*)&hs[r][k];
#pragma unroll
            for (int g = 0; g < 4; g++) {
                float4 wv = *(const float4*)&Whh[(size_t)(hh + 256 * g) * 256 + k];
#pragma unroll
                for (int r = 0; r < 4; r++) {
                    acc[g][r] = fmaf(wv.x, xv[r].x, acc[g][r]);
                    acc[g][r] = fmaf(wv.y, xv[r].y, acc[g][r]);
                    acc[g][r] = fmaf(wv.z, xv[r].z, acc[g][r]);
                    acc[g][r] = fmaf(wv.w, xv[r].w, acc[g][r]);
                }
            }
        }
        if (half == 1) {
#pragma unroll
            for (int g = 0; g < 4; g++)
#pragma unroll
                for (int r = 0; r < 4; r++) red[g * 4 + r][hh] = acc[g][r];
        }
        __syncthreads();
        if (half == 0) {
#pragma unroll
            for (int r = 0; r < 4; r++) {
                float pre[4];
#pragma unroll
                for (int g = 0; g < 4; g++) {
                    float hsum = acc[g][r] + red[g * 4 + r][hh];
                    float xv   = (t == 0) ? xst[g]
                               : fmaf(sa1[r], md1[g], sa0[r] * md0[g]);
                    pre[g] = ((hsum + xv) + bi1[g]) + bi2[g];
                }
                float ig = sigf(pre[0]);
                float fg = sigf(pre[1]);
                float gg = tanhf(pre[2]);
                float og = sigf(pre[3]);
                float c  = fg * creg[r] + ig * gg;
                creg[r]  = c;
                hs[r][hh] = og * tanhf(c);
            }
        }
        __syncthreads();

        // ================= qq = h @ gWq^T + gbq (K-split) ========================
        {
            float a[4] = {0.f, 0.f, 0.f, 0.f};
#pragma unroll 2
            for (int kg = 0; kg < 32; kg++) {
                int k = k0 + kg * 4;
                float4 wv = *(const float4*)&gWq[(size_t)hh * 256 + k];
#pragma unroll
                for (int r = 0; r < 4; r++) {
                    float4 hv = *(const float4*)&hs[r][k];
                    a[r] = fmaf(wv.x, hv.x, a[r]); a[r] = fmaf(wv.y, hv.y, a[r]);
                    a[r] = fmaf(wv.z, hv.z, a[r]); a[r] = fmaf(wv.w, hv.w, a[r]);
                }
            }
            if (half == 1) {
#pragma unroll
                for (int r = 0; r < 4; r++) red[r][hh] = a[r];
            }
            __syncthreads();
            if (half == 0) {
#pragma unroll
                for (int r = 0; r < 4; r++) qs[r][hh] = (a[r] + red[r][hh]) + gbq_t;
            }
        }
        __syncthreads();

        // ===== glimpse logits: 16 warps (r = w>>2, quarter = w&3, 25 s each) =====
        // 2x s-unroll with prefetch; per-s sum order bit-identical to R10.
        {
            int r  = w >> 2;
            int s0 = (w & 3) * 25;
            float qv[8];
#pragma unroll
            for (int k = 0; k < 8; k++) qv[k] = qs[r][k * 32 + lane];
            const float* base = &d_refg[(((size_t)(b0 + r)) * S + s0) * H];
            for (int si = 0; si < 24; si += 2) {
                const float* rpA = base + (size_t)si * H;
                const float* rpB = rpA + H;
                float xa[8], xb[8];
#pragma unroll
                for (int k = 0; k < 8; k++) {
                    xa[k] = __ldg(&rpA[k * 32 + lane]);
                    xb[k] = __ldg(&rpB[k * 32 + lane]);
                }
                float sA = 0.0f, sB = 0.0f;
#pragma unroll
                for (int k = 0; k < 8; k++) {
                    float v = __ldg(&gV[k * 32 + lane]);
                    sA = fmaf(v, tanhf(qv[k] + xa[k]), sA);
                    sB = fmaf(v, tanhf(qv[k] + xb[k]), sB);
                }
#pragma unroll
                for (int o = 16; o > 0; o >>= 1) {
                    sA += __shfl_xor_sync(0xffffffffu, sA, o);
                    sB += __shfl_xor_sync(0xffffffffu, sB, o);
                }
                if (lane == 0) {
                    lgm[r][s0 + si]     = msk[r][s0 + si]     ? neg_inf() : sA;
                    lgm[r][s0 + si + 1] = msk[r][s0 + si + 1] ? neg_inf() : sB;
                }
            }
            {   // tail s = s0 + 24
                int s = s0 + 24;
                const float* rp = base + (size_t)24 * H;
                float sum = 0.0f;
#pragma unroll
                for (int k = 0; k < 8; k++)
                    sum = fmaf(__ldg(&gV[k * 32 + lane]),
                               tanhf(qv[k] + __ldg(&rp[k * 32 + lane])), sum);
#pragma unroll
                for (int o = 16; o > 0; o >>= 1) sum += __shfl_xor_sync(0xffffffffu, sum, o);
                if (lane == 0) lgm[r][s] = msk[r][s] ? neg_inf() : sum;
            }
        }
        __syncthreads();

        // ================= glimpse softmax -> pr (bit-identical) =================
        if (w < 4) {
            int r = w;
            float v[4];
#pragma unroll
            for (int j = 0; j < 4; j++) {
                int s = lane + 32 * j;
                v[j] = (s < 100) ? lgm[r][s] : neg_inf();
            }
            float m = fmaxf(fmaxf(v[0], v[1]), fmaxf(v[2], v[3]));
#pragma unroll
            for (int o = 16; o > 0; o >>= 1) m = fmaxf(m, __shfl_xor_sync(0xffffffffu, m, o));
            float e[4];
#pragma unroll
            for (int j = 0; j < 4; j++) {
                int s = lane + 32 * j;
                e[j] = (s < 100) ? expf(v[j] - m) : 0.0f;
            }
            float sum = (e[0] + e[2]) + (e[1] + e[3]);
#pragma unroll
            for (int o = 16; o > 0; o >>= 1) sum += __shfl_xor_sync(0xffffffffu, sum, o);
#pragma unroll
            for (int j = 0; j < 4; j++) {
                int s = lane + 32 * j;
                if (s < 100) pr[r][s] = e[j] / sum;
            }
        }
        __syncthreads();

        // ================= readout: q = softmax(lg) @ enc (S-split by half) ======
        {
            float a[4] = {0.f, 0.f, 0.f, 0.f};
            int sBase = half * 50;
            for (int si = 0; si < 50; si++) {
                int s = sBase + si;
#pragma unroll
                for (int r = 0; r < 4; r++)
                    a[r] = fmaf(pr[r][s],
                                __ldg(&d_enc[(((size_t)(b0 + r)) * S + s) * H + hh]),
                                a[r]);
            }
            if (half == 1) {
#pragma unroll
                for (int r = 0; r < 4; r++) red[r][hh] = a[r];
            }
            __syncthreads();
            if (half == 0) {
#pragma unroll
                for (int r = 0; r < 4; r++) qs[r][hh] = a[r] + red[r][hh];
            }
        }
        __syncthreads();

        // ================= qp = q @ pWq^T + pbq (K-split) ========================
        {
            float a[4] = {0.f, 0.f, 0.f, 0.f};
#pragma unroll 2
            for (int kg = 0; kg < 32; kg++) {
                int k = k0 + kg * 4;
                float4 wv = *(const float4*)&pWq[(size_t)hh * 256 + k];
#pragma unroll
                for (int r = 0; r < 4; r++) {
                    float4 hv = *(const float4*)&qs[r][k];
                    a[r] = fmaf(wv.x, hv.x, a[r]); a[r] = fmaf(wv.y, hv.y, a[r]);
                    a[r] = fmaf(wv.z, hv.z, a[r]); a[r] = fmaf(wv.w, hv.w, a[r]);
                }
            }
            if (half == 1) {
#pragma unroll
                for (int r = 0; r < 4; r++) red[4 + r][hh] = a[r];
            }
            __syncthreads();
            if (half == 0) {
#pragma unroll
                for (int r = 0; r < 4; r++) qps[r][hh] = (a[r] + red[4 + r][hh]) + pbq_t;
            }
        }
        __syncthreads();

        // ================= pointer logits (same 2x unroll) =======================
        {
            int r  = w >> 2;
            int s0 = (w & 3) * 25;
            float qv[8];
#pragma unroll
            for (int k = 0; k < 8; k++) qv[k] = qps[r][k * 32 + lane];
            const float* base = &d_refp[(((size_t)(b0 + r)) * S + s0) * H];
            for (int si = 0; si < 24; si += 2) {
                const float* rpA = base + (size_t)si * H;
                const float* rpB = rpA + H;
                float xa[8], xb[8];
#pragma unroll
                for (int k = 0; k < 8; k++) {
                    xa[k] = __ldg(&rpA[k * 32 + lane]);
                    xb[k] = __ldg(&rpB[k * 32 + lane]);
                }
                float sA = 0.0f, sB = 0.0f;
#pragma unroll
                for (int k = 0; k < 8; k++) {
                    float v = __ldg(&pV[k * 32 + lane]);
                    sA = fmaf(v, tanhf(qv[k] + xa[k]), sA);
                    sB = fmaf(v, tanhf(qv[k] + xb[k]), sB);
                }
#pragma unroll
                for (int o = 16; o > 0; o >>= 1) {
                    sA += __shfl_xor_sync(0xffffffffu, sA, o);
                    sB += __shfl_xor_sync(0xffffffffu, sB, o);
                }
                if (lane == 0) {
                    lgm[r][s0 + si]     = msk[r][s0 + si]     ? neg_inf() : (10.0f * tanhf(sA));
                    lgm[r][s0 + si + 1] = msk[r][s0 + si + 1] ? neg_inf() : (10.0f * tanhf(sB));
                }
            }
            {   // tail s = s0 + 24
                int s = s0 + 24;
                const float* rp = base + (size_t)24 * H;
                float sum = 0.0f;
#pragma unroll
                for (int k = 0; k < 8; k++)
                    sum = fmaf(__ldg(&pV[k * 32 + lane]),
                               tanhf(qv[k] + __ldg(&rp[k * 32 + lane])), sum);
#pragma unroll
                for (int o = 16; o > 0; o >>= 1) sum += __shfl_xor_sync(0xffffffffu, sum, o);
                if (lane == 0) lgm[r][s] = msk[r][s] ? neg_inf() : (10.0f * tanhf(sum));
            }
        }
        __syncthreads();

        // ================= sample (bit-identical) ================================
        if (w < 4) {
            int r = w;
            int b = b0 + r;
            float v[4];
#pragma unroll
            for (int j = 0; j < 4; j++) {
                int s = lane + 32 * j;
                v[j] = (s < 100) ? lgm[r][s] : neg_inf();
            }
            float bv = neg_inf(); int bi = 0;
#pragma unroll
            for (int j = 0; j < 4; j++) {
                int s = lane + 32 * j;
                if (s < 100) {
                    float y = v[j] + d_gum[((size_t)t * B + b) * S + s];
                    if (y > bv) { bv = y; bi = s; }
                }
            }
#pragma unroll
            for (int o = 16; o > 0; o >>= 1) {
                float vo = __shfl_xor_sync(0xffffffffu, bv, o);
                int   io = __shfl_xor_sync(0xffffffffu, bi, o);
                if (vo > bv || (vo == bv && io < bi)) { bv = vo; bi = io; }
            }
            float m = fmaxf(fmaxf(v[0], v[1]), fmaxf(v[2], v[3]));
#pragma unroll
            for (int o = 16; o > 0; o >>= 1) m = fmaxf(m, __shfl_xor_sync(0xffffffffu, m, o));
            float e[4];
#pragma unroll
            for (int j = 0; j < 4; j++) {
                int s = lane + 32 * j;
                e[j] = (s < 100) ? expf(v[j] - m) : 0.0f;
            }
            float sum = (e[0] + e[2]) + (e[1] + e[3]);
#pragma unroll
            for (int o = 16; o > 0; o >>= 1) sum += __shfl_xor_sync(0xffffffffu, sum, o);
#pragma unroll
            for (int j = 0; j < 4; j++) {
                int s = lane + 32 * j;
                if (s < 100) out_probs[((size_t)t * B + b) * S + s] = e[j] / sum;
            }
            if (lane == 0) {
                msk[r][bi] = 1;
                out_idx[(size_t)t * B + b] = (float)bi;
                sa0[r] = inputs[((size_t)b * 2 + 0) * S + bi];
                sa1[r] = inputs[((size_t)b * 2 + 1) * S + bi];
            }
        }
        __syncthreads();
    }
}

// ---------------- host ----------------
extern "C" void kernel_launch(void* const* d_in, const int* in_sizes, int n_in,
                              void* d_out, int out_size)
{
    (void)in_sizes; (void)n_in; (void)out_size;
    const float* inputs  = (const float*)d_in[0];
    const float* emb     = (const float*)d_in[1];
    const float* enc_Wih = (const float*)d_in[2];
    const float* enc_Whh = (const float*)d_in[3];
    const float* enc_bih = (const float*)d_in[4];
    const float* enc_bhh = (const float*)d_in[5];
    const float* dec_Wih = (const float*)d_in[6];
    const float* dec_Whh = (const float*)d_in[7];
    const float* dec_bih = (const float*)d_in[8];
    const float* dec_bhh = (const float*)d_in[9];
    const float* g_Wq    = (const float*)d_in[10];
    const float* g_bq    = (const float*)d_in[11];
    const float* g_Wr    = (const float*)d_in[12];
    const float* g_br    = (const float*)d_in[13];
    const float* g_V     = (const float*)d_in[14];
    const float* p_Wq    = (const float*)d_in[15];
    const float* p_bq    = (const float*)d_in[16];
    const float* p_Wr    = (const float*)d_in[17];
    const float* p_br    = (const float*)d_in[18];
    const float* p_V     = (const float*)d_in[19];
    const float* start   = (const float*)d_in[20];

    float* out       = (float*)d_out;
    float* out_probs = out;                              // [S,B,S]
    float* out_idx   = out + (size_t)S * B * S;          // [S,B] (as float)

    gumbelk <<<(S * B * S + 255) / 256, 256>>>();
    precompk<<<4, 256>>>(emb, enc_Wih, dec_Wih, start);

    encoderk<<<B / 4, 512>>>(inputs, enc_Whh, enc_bih, enc_bhh,
                             g_Wr, g_br, p_Wr, p_br);

    decoderk<<<B / 4, 512>>>(inputs, dec_Whh, dec_bih, dec_bhh,
                             g_Wq, g_bq, g_V, p_Wq, p_bq, p_V,
                             out_probs, out_idx);
}